// round 1
// baseline (speedup 1.0000x reference)
#include <cuda_runtime.h>
#include <cuda_bf16.h>
#include <cstddef>

// ---------------------------------------------------------------------------
// Shapes (fixed): B=8, S=256, EMB=512, HID=256, NH=8, DH=32
// Outputs concat: cons[8] | hall[8] | M[8*256*256] | attn_weights[8*256*256]
// ---------------------------------------------------------------------------

#define Bn 8
#define Sn 256
#define EMB 512
#define HID 256
#define NHh 8
#define DHd 32
#define ROWS (Bn*Sn)          // 2048

// Scratch (no allocs allowed -> __device__ globals)
__device__ float g_h[ROWS*HID];
__device__ float g_r[ROWS*HID];
__device__ float g_mf[ROWS*HID];
__device__ float g_qkv[ROWS*3*HID];
__device__ float g_ctx[ROWS*HID];
__device__ float g_att[ROWS*HID];
__device__ float g_a[ROWS*HID];
__device__ float g_b[ROWS*HID];
__device__ float g_probs[NHh*Bn*Sn*Sn];   // [h][b][t][s], pre-scaled by 1/NH
__device__ float g_pooled[Bn*HID];

// ---------------------------------------------------------------------------
// Generic fp32 GEMM:  C[M,N] = A[M,K] @ W^T (+bias)
//   A row-major (lda=K), W row-major N x ldw, element W[n*ldw + k]
//   64x64 tile, BK=16, 256 threads, 4x4 microtile.
// ---------------------------------------------------------------------------
__global__ void gemm_tn_kernel(const float* __restrict__ A,
                               const float* __restrict__ W,
                               const float* __restrict__ bias,
                               float* __restrict__ C,
                               int M, int N, int K, int ldw)
{
    __shared__ float As[16][64];
    __shared__ float Ws[16][64];
    int tid = threadIdx.x;
    int ar = tid >> 2;            // 0..63
    int ac = (tid & 3) << 2;      // 0,4,8,12
    int row0 = blockIdx.y << 6;
    int col0 = blockIdx.x << 6;
    const float* Ap = A + (size_t)(row0 + ar) * K + ac;
    const float* Wp = W + (size_t)(col0 + ar) * ldw + ac;
    int tx = tid & 15, ty = tid >> 4;

    float acc[4][4];
#pragma unroll
    for (int i = 0; i < 4; i++)
#pragma unroll
        for (int j = 0; j < 4; j++) acc[i][j] = 0.f;

    for (int k0 = 0; k0 < K; k0 += 16) {
        float4 av = *(const float4*)(Ap + k0);
        float4 wv = *(const float4*)(Wp + k0);
        As[ac + 0][ar] = av.x; As[ac + 1][ar] = av.y;
        As[ac + 2][ar] = av.z; As[ac + 3][ar] = av.w;
        Ws[ac + 0][ar] = wv.x; Ws[ac + 1][ar] = wv.y;
        Ws[ac + 2][ar] = wv.z; Ws[ac + 3][ar] = wv.w;
        __syncthreads();
#pragma unroll
        for (int kk = 0; kk < 16; kk++) {
            float a[4], w[4];
#pragma unroll
            for (int i = 0; i < 4; i++) a[i] = As[kk][ty + (i << 4)];
#pragma unroll
            for (int j = 0; j < 4; j++) w[j] = Ws[kk][tx + (j << 4)];
#pragma unroll
            for (int i = 0; i < 4; i++)
#pragma unroll
                for (int j = 0; j < 4; j++) acc[i][j] += a[i] * w[j];
        }
        __syncthreads();
    }

#pragma unroll
    for (int i = 0; i < 4; i++) {
        int r = row0 + ty + (i << 4);
#pragma unroll
        for (int j = 0; j < 4; j++) {
            int c = col0 + tx + (j << 4);
            float v = acc[i][j];
            if (bias) v += bias[c];
            C[(size_t)r * N + c] = v;
        }
    }
}

// ---------------------------------------------------------------------------
// LayerNorm(HID=256) + ReLU, one block per row.
// ---------------------------------------------------------------------------
__global__ void ln_relu_kernel(const float* __restrict__ h,
                               const float* __restrict__ g,
                               const float* __restrict__ beta,
                               float* __restrict__ out)
{
    int row = blockIdx.x;
    int c = threadIdx.x;
    float v = h[(size_t)row * HID + c];
    float s = v, s2 = v * v;
#pragma unroll
    for (int o = 16; o; o >>= 1) {
        s  += __shfl_xor_sync(0xffffffffu, s, o);
        s2 += __shfl_xor_sync(0xffffffffu, s2, o);
    }
    __shared__ float rs[8], rs2[8];
    if ((c & 31) == 0) { rs[c >> 5] = s; rs2[c >> 5] = s2; }
    __syncthreads();
    float tot = 0.f, tot2 = 0.f;
#pragma unroll
    for (int w = 0; w < 8; w++) { tot += rs[w]; tot2 += rs2[w]; }
    float mu = tot * (1.f / 256.f);
    float var = tot2 * (1.f / 256.f) - mu * mu;
    float y = (v - mu) * rsqrtf(var + 1e-5f) * g[c] + beta[c];
    out[(size_t)row * HID + c] = fmaxf(y, 0.f);
}

// ---------------------------------------------------------------------------
// Attention: one block per (b,h), 256 threads (one per query s).
// Pass 1: online softmax -> ctx. Pass 2: write probs/NH to scratch [h][b][t][s].
// Dynamic smem: K tile + V tile (2 * 256*32 floats = 64 KB).
// ---------------------------------------------------------------------------
__global__ void attn_kernel(const float* __restrict__ qkv,
                            float* __restrict__ ctx,
                            float* __restrict__ probs)
{
    extern __shared__ float sm[];
    float* Ks = sm;             // [256][32]
    float* Vs = sm + 256 * 32;  // [256][32]
    int bh = blockIdx.x;
    int b = bh >> 3, hd = bh & 7;
    int s = threadIdx.x;
    const float* base = qkv + (size_t)(b * Sn) * (3 * HID) + hd * DHd;

    {
        const float4* krow = (const float4*)(base + (size_t)s * (3 * HID) + HID);
        const float4* vrow = (const float4*)(base + (size_t)s * (3 * HID) + 2 * HID);
        float4* kd = (float4*)(Ks + s * 32);
        float4* vd = (float4*)(Vs + s * 32);
#pragma unroll
        for (int i = 0; i < 8; i++) { kd[i] = krow[i]; vd[i] = vrow[i]; }
    }
    float q[32];
    {
        const float4* qrow = (const float4*)(base + (size_t)s * (3 * HID));
#pragma unroll
        for (int i = 0; i < 8; i++) {
            float4 t = qrow[i];
            q[4 * i] = t.x; q[4 * i + 1] = t.y; q[4 * i + 2] = t.z; q[4 * i + 3] = t.w;
        }
    }
    __syncthreads();

    const float scale = 0.17677669529663687f;   // 1/sqrt(32)
    float m = -1e30f, l = 0.f;
    float acc[32];
#pragma unroll
    for (int d = 0; d < 32; d++) acc[d] = 0.f;

    for (int t = 0; t < Sn; t++) {
        const float4* k4 = (const float4*)(Ks + t * 32);
        float sd = 0.f;
#pragma unroll
        for (int i = 0; i < 8; i++) {
            float4 kv = k4[i];
            sd += q[4 * i] * kv.x + q[4 * i + 1] * kv.y
                + q[4 * i + 2] * kv.z + q[4 * i + 3] * kv.w;
        }
        sd *= scale;
        float mn = fmaxf(m, sd);
        float corr = __expf(m - mn);
        float p = __expf(sd - mn);
        l = l * corr + p;
        const float4* v4 = (const float4*)(Vs + t * 32);
#pragma unroll
        for (int i = 0; i < 8; i++) {
            float4 vv = v4[i];
            acc[4 * i]     = acc[4 * i]     * corr + p * vv.x;
            acc[4 * i + 1] = acc[4 * i + 1] * corr + p * vv.y;
            acc[4 * i + 2] = acc[4 * i + 2] * corr + p * vv.z;
            acc[4 * i + 3] = acc[4 * i + 3] * corr + p * vv.w;
        }
        m = mn;
    }
    float invl = 1.f / l;
    float* crow = ctx + (size_t)(b * Sn + s) * HID + hd * DHd;
#pragma unroll
    for (int i = 0; i < 8; i++) {
        float4 o;
        o.x = acc[4 * i] * invl;     o.y = acc[4 * i + 1] * invl;
        o.z = acc[4 * i + 2] * invl; o.w = acc[4 * i + 3] * invl;
        ((float4*)crow)[i] = o;
    }

    // pass 2: probs[h][b][t][s] = exp(score - m)/l / NH  (coalesced over s)
    float* pb = probs + ((size_t)(hd * Bn + b) * Sn) * Sn + s;
    float c1 = invl * 0.125f;
    for (int t = 0; t < Sn; t++) {
        const float4* k4 = (const float4*)(Ks + t * 32);
        float sd = 0.f;
#pragma unroll
        for (int i = 0; i < 8; i++) {
            float4 kv = k4[i];
            sd += q[4 * i] * kv.x + q[4 * i + 1] * kv.y
                + q[4 * i + 2] * kv.z + q[4 * i + 3] * kv.w;
        }
        pb[(size_t)t * Sn] = __expf(sd * scale - m) * c1;
    }
}

// ---------------------------------------------------------------------------
// attn_weights[b][s][t] = sum_h probs[h][b][t][s]   (transpose via smem tile)
// grid (8 t-tiles, 8 s-tiles, 8 b), block (32,8)
// ---------------------------------------------------------------------------
__global__ void attnw_kernel(const float* __restrict__ probs,
                             float* __restrict__ out)
{
    __shared__ float tile[32][33];
    int b = blockIdx.z, t0 = blockIdx.x * 32, s0 = blockIdx.y * 32;
    int tx = threadIdx.x, ty = threadIdx.y;
#pragma unroll
    for (int r = 0; r < 4; r++) {
        int t = t0 + ty + r * 8;
        float sum = 0.f;
#pragma unroll
        for (int h = 0; h < 8; h++)
            sum += probs[((size_t)(h * Bn + b) * Sn + t) * Sn + s0 + tx];
        tile[ty + r * 8][tx] = sum;
    }
    __syncthreads();
#pragma unroll
    for (int r = 0; r < 4; r++) {
        int srow = s0 + ty + r * 8;
        out[((size_t)b * Sn + srow) * Sn + t0 + tx] = tile[tx][ty + r * 8];
    }
}

// ---------------------------------------------------------------------------
// pooled[b][c] = mean_s attended[b][s][c]
// ---------------------------------------------------------------------------
__global__ void pool_kernel(const float* __restrict__ att, float* __restrict__ pooled)
{
    int b = blockIdx.x, c = threadIdx.x;
    float s = 0.f;
    for (int t = 0; t < Sn; t++) s += att[(size_t)(b * Sn + t) * HID + c];
    pooled[b * HID + c] = s * (1.f / 256.f);
}

// ---------------------------------------------------------------------------
// cons/hall scalar MLPs: grid 16 = (b,which), 128 threads.
// ---------------------------------------------------------------------------
__global__ void head_mlp_kernel(const float* __restrict__ pooled,
                                const float* __restrict__ cw1, const float* __restrict__ cb1,
                                const float* __restrict__ cw2, const float* __restrict__ cb2,
                                const float* __restrict__ hw1, const float* __restrict__ hb1,
                                const float* __restrict__ hw2, const float* __restrict__ hb2,
                                float* __restrict__ out)
{
    int b = blockIdx.x >> 1;
    int which = blockIdx.x & 1;
    const float* w1 = which ? hw1 : cw1;
    const float* b1 = which ? hb1 : cb1;
    const float* w2 = which ? hw2 : cw2;
    const float* b2 = which ? hb2 : cb2;
    int tid = threadIdx.x;
    __shared__ float p[256];
    p[tid] = pooled[b * HID + tid];
    p[tid + 128] = pooled[b * HID + tid + 128];
    __syncthreads();
    float acc = b1[tid];
    const float* wrow = w1 + (size_t)tid * HID;
#pragma unroll 8
    for (int k = 0; k < HID; k++) acc += p[k] * wrow[k];
    float v = fmaxf(acc, 0.f) * w2[tid];
#pragma unroll
    for (int o = 16; o; o >>= 1) v += __shfl_xor_sync(0xffffffffu, v, o);
    __shared__ float rs[4];
    if ((tid & 31) == 0) rs[tid >> 5] = v;
    __syncthreads();
    if (tid == 0) {
        float sum = rs[0] + rs[1] + rs[2] + rs[3] + b2[0];
        out[which * 8 + b] = 1.f / (1.f + __expf(-sum));
    }
}

// ---------------------------------------------------------------------------
// Zero the diagonal of M (rest fully overwritten by pair kernel).
// ---------------------------------------------------------------------------
__global__ void zero_diag_kernel(float* __restrict__ M)
{
    int b = blockIdx.x, i = threadIdx.x;
    M[(size_t)b * Sn * Sn + (size_t)i * Sn + i] = 0.f;
}

// ---------------------------------------------------------------------------
// Pairwise consistency matrix.
//   sc(b,i,j) = sigmoid( sum_c relu(a[b,i,c] + bb[b,j,c] + con_b1[c]) * w2[c] + b2 )
//   M[b,i,j] = M[b,j,i] = sc  for i<j; diag zero.
// grid (tj=8, ti=8, b=8), block 256, tiles 32x32, dynamic smem ~70 KB.
// ---------------------------------------------------------------------------
__global__ void pair_kernel(const float* __restrict__ ga, const float* __restrict__ gb,
                            const float* __restrict__ b1, const float* __restrict__ w2,
                            const float* __restrict__ b2, float* __restrict__ M)
{
    int tj = blockIdx.x, ti = blockIdx.y, b = blockIdx.z;
    if (ti > tj) return;
    extern __shared__ float sm[];
    float* a_s = sm;                 // [32][256]  (bias folded in)
    float* bT  = sm + 32 * 256;      // [256][32]  transposed
    float* w2s = sm + 2 * 32 * 256;  // [256]
    float* scs = w2s + 256;          // [32][33]
    int tid = threadIdx.x;
    {
        int r = tid >> 3;
        int cb = (tid & 7) * 32;
        const float4* asrc = (const float4*)(ga + (size_t)(b * Sn + ti * 32 + r) * HID + cb);
        const float4* bsrc = (const float4*)(gb + (size_t)(b * Sn + tj * 32 + r) * HID + cb);
#pragma unroll
        for (int u = 0; u < 8; u++) {
            int c = cb + u * 4;
            float4 av = asrc[u];
            a_s[r * 256 + c + 0] = av.x + b1[c + 0];
            a_s[r * 256 + c + 1] = av.y + b1[c + 1];
            a_s[r * 256 + c + 2] = av.z + b1[c + 2];
            a_s[r * 256 + c + 3] = av.w + b1[c + 3];
            float4 bv = bsrc[u];
            bT[(c + 0) * 32 + r] = bv.x;
            bT[(c + 1) * 32 + r] = bv.y;
            bT[(c + 2) * 32 + r] = bv.z;
            bT[(c + 3) * 32 + r] = bv.w;
        }
        w2s[tid] = w2[tid];
    }
    __syncthreads();

    int tx = tid & 31, ty = tid >> 5;  // tx = j-local, ty in 0..7
    float acc[4] = {0.f, 0.f, 0.f, 0.f};
    for (int c = 0; c < 256; c++) {
        float bv = bT[c * 32 + tx];
        float w = w2s[c];
#pragma unroll
        for (int ii = 0; ii < 4; ii++) {
            float t = a_s[(ty + 8 * ii) * 256 + c] + bv;
            acc[ii] += fmaxf(t, 0.f) * w;
        }
    }
    float bb2 = b2[0];
#pragma unroll
    for (int ii = 0; ii < 4; ii++) {
        int il = ty + 8 * ii;
        float sc = 1.f / (1.f + __expf(-(acc[ii] + bb2)));
        scs[il * 33 + tx] = ((ti * 32 + il) < (tj * 32 + tx)) ? sc : 0.f;
    }
    __syncthreads();

    float* Mb = M + (size_t)b * Sn * Sn;
    bool diag = (ti == tj);
#pragma unroll
    for (int ii = 0; ii < 4; ii++) {
        int il = ty + 8 * ii;
        if (!diag || il < tx)
            Mb[(size_t)(ti * 32 + il) * Sn + tj * 32 + tx] = scs[il * 33 + tx];
        if (!diag || tx < il)
            Mb[(size_t)(tj * 32 + il) * Sn + ti * 32 + tx] = scs[tx * 33 + il];
    }
}

// ---------------------------------------------------------------------------
// Host launcher
// ---------------------------------------------------------------------------
extern "C" void kernel_launch(void* const* d_in, const int* in_sizes, int n_in,
                              void* d_out, int out_size)
{
    (void)in_sizes; (void)n_in; (void)out_size;
    const float* X        = (const float*)d_in[0];
    const float* enc_w1   = (const float*)d_in[1];
    const float* enc_b1   = (const float*)d_in[2];
    const float* ln_g     = (const float*)d_in[3];
    const float* ln_b     = (const float*)d_in[4];
    const float* enc_w2   = (const float*)d_in[5];
    const float* enc_b2   = (const float*)d_in[6];
    const float* in_proj_w= (const float*)d_in[7];
    const float* in_proj_b= (const float*)d_in[8];
    const float* out_w    = (const float*)d_in[9];
    const float* out_b    = (const float*)d_in[10];
    const float* cons_w1  = (const float*)d_in[11];
    const float* cons_b1  = (const float*)d_in[12];
    const float* cons_w2  = (const float*)d_in[13];
    const float* cons_b2  = (const float*)d_in[14];
    const float* hall_w1  = (const float*)d_in[15];
    const float* hall_b1  = (const float*)d_in[16];
    const float* hall_w2  = (const float*)d_in[17];
    const float* hall_b2  = (const float*)d_in[18];
    const float* con_w1   = (const float*)d_in[19];
    const float* con_b1   = (const float*)d_in[20];
    const float* con_w2   = (const float*)d_in[21];
    const float* con_b2   = (const float*)d_in[22];

    float* out = (float*)d_out;
    float* Mout  = out + 16;
    float* AWout = out + 16 + Bn * Sn * Sn;

    float *p_h, *p_r, *p_mf, *p_qkv, *p_ctx, *p_att, *p_a, *p_b, *p_probs, *p_pooled;
    cudaGetSymbolAddress((void**)&p_h, g_h);
    cudaGetSymbolAddress((void**)&p_r, g_r);
    cudaGetSymbolAddress((void**)&p_mf, g_mf);
    cudaGetSymbolAddress((void**)&p_qkv, g_qkv);
    cudaGetSymbolAddress((void**)&p_ctx, g_ctx);
    cudaGetSymbolAddress((void**)&p_att, g_att);
    cudaGetSymbolAddress((void**)&p_a, g_a);
    cudaGetSymbolAddress((void**)&p_b, g_b);
    cudaGetSymbolAddress((void**)&p_probs, g_probs);
    cudaGetSymbolAddress((void**)&p_pooled, g_pooled);

    const int attn_smem = 2 * 256 * 32 * (int)sizeof(float);           // 64 KB
    const int pair_smem = (2 * 32 * 256 + 256 + 32 * 33) * (int)sizeof(float); // ~70 KB
    cudaFuncSetAttribute(attn_kernel, cudaFuncAttributeMaxDynamicSharedMemorySize, attn_smem);
    cudaFuncSetAttribute(pair_kernel, cudaFuncAttributeMaxDynamicSharedMemorySize, pair_smem);

    // 1. h = X @ enc_w1^T + enc_b1          [2048,256] K=512
    gemm_tn_kernel<<<dim3(HID / 64, ROWS / 64), 256>>>(X, enc_w1, enc_b1, p_h, ROWS, HID, EMB, EMB);
    // 2. r = relu(LN(h))
    ln_relu_kernel<<<ROWS, 256>>>(p_h, ln_g, ln_b, p_r);
    // 3. mf = r @ enc_w2^T + enc_b2
    gemm_tn_kernel<<<dim3(HID / 64, ROWS / 64), 256>>>(p_r, enc_w2, enc_b2, p_mf, ROWS, HID, HID, HID);
    // 4. qkv = mf @ in_proj_w^T + in_proj_b  [2048,768]
    gemm_tn_kernel<<<dim3(3 * HID / 64, ROWS / 64), 256>>>(p_mf, in_proj_w, in_proj_b, p_qkv, ROWS, 3 * HID, HID, HID);
    // 5. attention -> ctx, probs
    attn_kernel<<<Bn * NHh, 256, attn_smem>>>(p_qkv, p_ctx, p_probs);
    // 6. attended = ctx @ out_w^T + out_b
    gemm_tn_kernel<<<dim3(HID / 64, ROWS / 64), 256>>>(p_ctx, out_w, out_b, p_att, ROWS, HID, HID, HID);
    // 7. attn_weights (head mean + transpose)
    attnw_kernel<<<dim3(8, 8, 8), dim3(32, 8)>>>(p_probs, AWout);
    // 8. pooled
    pool_kernel<<<Bn, 256>>>(p_att, p_pooled);
    // 9. cons/hall
    head_mlp_kernel<<<16, 128>>>(p_pooled, cons_w1, cons_b1, cons_w2, cons_b2,
                                 hall_w1, hall_b1, hall_w2, hall_b2, out);
    // 10/11. a = mf @ Wa^T, b = mf @ Wb^T  (Wa/Wb = halves of con_w1 (256x512))
    gemm_tn_kernel<<<dim3(HID / 64, ROWS / 64), 256>>>(p_mf, con_w1, nullptr, p_a, ROWS, HID, HID, 2 * HID);
    gemm_tn_kernel<<<dim3(HID / 64, ROWS / 64), 256>>>(p_mf, con_w1 + HID, nullptr, p_b, ROWS, HID, HID, 2 * HID);
    // 12. zero diagonal of M
    zero_diag_kernel<<<Bn, Sn>>>(Mout);
    // 13. pairwise M
    pair_kernel<<<dim3(8, 8, 8), 256, pair_smem>>>(p_a, p_b, con_b1, con_w2, con_b2, Mout);
}

// round 2
// speedup vs baseline: 1.2415x; 1.2415x over previous
#include <cuda_runtime.h>
#include <cuda_bf16.h>
#include <cstddef>

// ---------------------------------------------------------------------------
// Shapes (fixed): B=8, S=256, EMB=512, HID=256, NH=8, DH=32
// Outputs concat: cons[8] | hall[8] | M[8*256*256] | attn_weights[8*256*256]
// ---------------------------------------------------------------------------

#define Bn 8
#define Sn 256
#define EMB 512
#define HID 256
#define NHh 8
#define DHd 32
#define ROWS (Bn*Sn)          // 2048

// Scratch (no allocs allowed -> __device__ globals)
__device__ float g_h[ROWS*HID];
__device__ float g_r[ROWS*HID];
__device__ float g_mf[ROWS*HID];
__device__ float g_qkv[ROWS*3*HID];
__device__ float g_ctx[ROWS*HID];
__device__ float g_att[ROWS*HID];
__device__ float g_a[ROWS*HID];
__device__ float g_b[ROWS*HID];
__device__ float g_probs[NHh*Bn*Sn*Sn];   // [h][b][t][s]
__device__ float g_pooled[Bn*HID];

// ---------------------------------------------------------------------------
// fp32 GEMM v2:  C[M,N] = A[M,K] @ W^T (+bias)
//   A row-major (lda=K), W row-major [N][ldw] (element W[n*ldw+k])
//   64x64 tile, BK=16, 128 threads, 8x4 microtile, float4 smem loads,
//   double-buffered smem with register prefetch.
// ---------------------------------------------------------------------------
__global__ void gemm2_kernel(const float* __restrict__ A,
                             const float* __restrict__ W,
                             const float* __restrict__ bias,
                             float* __restrict__ C,
                             int N, int K, int ldw)
{
    __shared__ __align__(16) float As[2][16][68];
    __shared__ __align__(16) float Ws[2][16][68];
    const int tid = threadIdx.x;
    const int row0 = blockIdx.y << 6;
    const int col0 = blockIdx.x << 6;

    // loader role: 64 rows x 16 k; each thread loads 8 k-floats for one row
    const int lrow = tid & 63;
    const int lk = (tid >> 6) << 3;   // 0 or 8
    const float* Ap = A + (size_t)(row0 + lrow) * K + lk;
    const float* Wp = W + (size_t)(col0 + lrow) * ldw + lk;

    // compute role: 16 tx (4 cols each) x 8 ty (8 rows each)
    const int tx = tid & 15;
    const int ty = tid >> 4;

    float acc[8][4];
#pragma unroll
    for (int i = 0; i < 8; i++)
#pragma unroll
        for (int j = 0; j < 4; j++) acc[i][j] = 0.f;

    // prefetch tile 0
    float4 a0 = *(const float4*)(Ap);
    float4 a1 = *(const float4*)(Ap + 4);
    float4 w0 = *(const float4*)(Wp);
    float4 w1 = *(const float4*)(Wp + 4);
    As[0][lk + 0][lrow] = a0.x; As[0][lk + 1][lrow] = a0.y;
    As[0][lk + 2][lrow] = a0.z; As[0][lk + 3][lrow] = a0.w;
    As[0][lk + 4][lrow] = a1.x; As[0][lk + 5][lrow] = a1.y;
    As[0][lk + 6][lrow] = a1.z; As[0][lk + 7][lrow] = a1.w;
    Ws[0][lk + 0][lrow] = w0.x; Ws[0][lk + 1][lrow] = w0.y;
    Ws[0][lk + 2][lrow] = w0.z; Ws[0][lk + 3][lrow] = w0.w;
    Ws[0][lk + 4][lrow] = w1.x; Ws[0][lk + 5][lrow] = w1.y;
    Ws[0][lk + 6][lrow] = w1.z; Ws[0][lk + 7][lrow] = w1.w;
    __syncthreads();

    const int nt = K >> 4;
    for (int t = 0; t < nt; ++t) {
        const int cur = t & 1;
        if (t + 1 < nt) {
            const float* Ap2 = Ap + ((t + 1) << 4);
            const float* Wp2 = Wp + ((t + 1) << 4);
            a0 = *(const float4*)(Ap2);
            a1 = *(const float4*)(Ap2 + 4);
            w0 = *(const float4*)(Wp2);
            w1 = *(const float4*)(Wp2 + 4);
        }
#pragma unroll
        for (int kk = 0; kk < 16; ++kk) {
            float4 bf = *(const float4*)&Ws[cur][kk][tx << 2];
            float4 ra0 = *(const float4*)&As[cur][kk][ty << 3];
            float4 ra1 = *(const float4*)&As[cur][kk][(ty << 3) + 4];
            float av[8] = {ra0.x, ra0.y, ra0.z, ra0.w, ra1.x, ra1.y, ra1.z, ra1.w};
            float bv[4] = {bf.x, bf.y, bf.z, bf.w};
#pragma unroll
            for (int i = 0; i < 8; i++)
#pragma unroll
                for (int j = 0; j < 4; j++) acc[i][j] += av[i] * bv[j];
        }
        if (t + 1 < nt) {
            const int nb = (t + 1) & 1;
            As[nb][lk + 0][lrow] = a0.x; As[nb][lk + 1][lrow] = a0.y;
            As[nb][lk + 2][lrow] = a0.z; As[nb][lk + 3][lrow] = a0.w;
            As[nb][lk + 4][lrow] = a1.x; As[nb][lk + 5][lrow] = a1.y;
            As[nb][lk + 6][lrow] = a1.z; As[nb][lk + 7][lrow] = a1.w;
            Ws[nb][lk + 0][lrow] = w0.x; Ws[nb][lk + 1][lrow] = w0.y;
            Ws[nb][lk + 2][lrow] = w0.z; Ws[nb][lk + 3][lrow] = w0.w;
            Ws[nb][lk + 4][lrow] = w1.x; Ws[nb][lk + 5][lrow] = w1.y;
            Ws[nb][lk + 6][lrow] = w1.z; Ws[nb][lk + 7][lrow] = w1.w;
            __syncthreads();
        }
    }

    float4 bz = make_float4(0.f, 0.f, 0.f, 0.f);
    if (bias) bz = *(const float4*)(bias + col0 + (tx << 2));
#pragma unroll
    for (int i = 0; i < 8; i++) {
        int r = row0 + (ty << 3) + i;
        float4 o;
        o.x = acc[i][0] + bz.x; o.y = acc[i][1] + bz.y;
        o.z = acc[i][2] + bz.z; o.w = acc[i][3] + bz.w;
        *(float4*)(C + (size_t)r * N + col0 + (tx << 2)) = o;
    }
}

// ---------------------------------------------------------------------------
// LayerNorm(HID=256) + ReLU, one block per row.
// ---------------------------------------------------------------------------
__global__ void ln_relu_kernel(const float* __restrict__ h,
                               const float* __restrict__ g,
                               const float* __restrict__ beta,
                               float* __restrict__ out)
{
    int row = blockIdx.x;
    int c = threadIdx.x;
    float v = h[(size_t)row * HID + c];
    float s = v, s2 = v * v;
#pragma unroll
    for (int o = 16; o; o >>= 1) {
        s  += __shfl_xor_sync(0xffffffffu, s, o);
        s2 += __shfl_xor_sync(0xffffffffu, s2, o);
    }
    __shared__ float rs[8], rs2[8];
    if ((c & 31) == 0) { rs[c >> 5] = s; rs2[c >> 5] = s2; }
    __syncthreads();
    float tot = 0.f, tot2 = 0.f;
#pragma unroll
    for (int w = 0; w < 8; w++) { tot += rs[w]; tot2 += rs2[w]; }
    float mu = tot * (1.f / 256.f);
    float var = tot2 * (1.f / 256.f) - mu * mu;
    float y = (v - mu) * rsqrtf(var + 1e-5f) * g[c] + beta[c];
    out[(size_t)row * HID + c] = fmaxf(y, 0.f);
}

// ---------------------------------------------------------------------------
// Attention v2: grid = 128 blocks (2 query-halves x 64 (b,h)), 128 threads.
// Pass 1: online softmax -> ctx, stores raw scaled scores to probs buffer.
// Pass 2: reload score, write exp(score - m)/l/NH (no recompute).
// Dynamic smem: K + V tiles (64 KB).
// ---------------------------------------------------------------------------
__global__ void attn2_kernel(const float* __restrict__ qkv,
                             float* __restrict__ ctx,
                             float* __restrict__ probs)
{
    extern __shared__ float sm[];
    float* Ks = sm;             // [256][32]
    float* Vs = sm + 256 * 32;  // [256][32]
    int bh = blockIdx.x >> 1;
    int half = blockIdx.x & 1;
    int b = bh >> 3, hd = bh & 7;
    int tid = threadIdx.x;         // 128
    int s = (half << 7) + tid;
    const float* base = qkv + (size_t)(b * Sn) * (3 * HID) + hd * DHd;

#pragma unroll
    for (int rr = 0; rr < 2; rr++) {
        int r = tid + rr * 128;
        const float4* krow = (const float4*)(base + (size_t)r * (3 * HID) + HID);
        const float4* vrow = (const float4*)(base + (size_t)r * (3 * HID) + 2 * HID);
        float4* kd = (float4*)(Ks + r * 32);
        float4* vd = (float4*)(Vs + r * 32);
#pragma unroll
        for (int i = 0; i < 8; i++) { kd[i] = krow[i]; vd[i] = vrow[i]; }
    }
    float q[32];
    {
        const float4* qrow = (const float4*)(base + (size_t)s * (3 * HID));
#pragma unroll
        for (int i = 0; i < 8; i++) {
            float4 t = qrow[i];
            q[4 * i] = t.x; q[4 * i + 1] = t.y; q[4 * i + 2] = t.z; q[4 * i + 3] = t.w;
        }
    }
    __syncthreads();

    const float scale = 0.17677669529663687f;   // 1/sqrt(32)
    float m = -1e30f, l = 0.f;
    float acc[32];
#pragma unroll
    for (int d = 0; d < 32; d++) acc[d] = 0.f;

    float* pb = probs + ((size_t)(hd * Bn + b) * Sn) * Sn + s;

    for (int t = 0; t < Sn; t++) {
        const float4* k4 = (const float4*)(Ks + t * 32);
        float sd = 0.f;
#pragma unroll
        for (int i = 0; i < 8; i++) {
            float4 kv = k4[i];
            sd += q[4 * i] * kv.x + q[4 * i + 1] * kv.y
                + q[4 * i + 2] * kv.z + q[4 * i + 3] * kv.w;
        }
        sd *= scale;
        pb[(size_t)t * Sn] = sd;          // stash raw score
        float mn = fmaxf(m, sd);
        float corr = __expf(m - mn);
        float p = __expf(sd - mn);
        l = l * corr + p;
        const float4* v4 = (const float4*)(Vs + t * 32);
#pragma unroll
        for (int i = 0; i < 8; i++) {
            float4 vv = v4[i];
            acc[4 * i]     = acc[4 * i]     * corr + p * vv.x;
            acc[4 * i + 1] = acc[4 * i + 1] * corr + p * vv.y;
            acc[4 * i + 2] = acc[4 * i + 2] * corr + p * vv.z;
            acc[4 * i + 3] = acc[4 * i + 3] * corr + p * vv.w;
        }
        m = mn;
    }
    float invl = 1.f / l;
    float* crow = ctx + (size_t)(b * Sn + s) * HID + hd * DHd;
#pragma unroll
    for (int i = 0; i < 8; i++) {
        float4 o;
        o.x = acc[4 * i] * invl;     o.y = acc[4 * i + 1] * invl;
        o.z = acc[4 * i + 2] * invl; o.w = acc[4 * i + 3] * invl;
        ((float4*)crow)[i] = o;
    }

    // pass 2: convert stashed scores to probs/NH
    float c1 = invl * 0.125f;
    for (int t = 0; t < Sn; t++) {
        float sc = pb[(size_t)t * Sn];
        pb[(size_t)t * Sn] = __expf(sc - m) * c1;
    }
}

// ---------------------------------------------------------------------------
// attn_weights[b][s][t] = sum_h probs[h][b][t][s]   (transpose via smem tile)
// ---------------------------------------------------------------------------
__global__ void attnw_kernel(const float* __restrict__ probs,
                             float* __restrict__ out)
{
    __shared__ float tile[32][33];
    int b = blockIdx.z, t0 = blockIdx.x * 32, s0 = blockIdx.y * 32;
    int tx = threadIdx.x, ty = threadIdx.y;
#pragma unroll
    for (int r = 0; r < 4; r++) {
        int t = t0 + ty + r * 8;
        float sum = 0.f;
#pragma unroll
        for (int h = 0; h < 8; h++)
            sum += probs[((size_t)(h * Bn + b) * Sn + t) * Sn + s0 + tx];
        tile[ty + r * 8][tx] = sum;
    }
    __syncthreads();
#pragma unroll
    for (int r = 0; r < 4; r++) {
        int srow = s0 + ty + r * 8;
        out[((size_t)b * Sn + srow) * Sn + t0 + tx] = tile[tx][ty + r * 8];
    }
}

// ---------------------------------------------------------------------------
// pooled[b][c] = mean_s attended[b][s][c]
// ---------------------------------------------------------------------------
__global__ void pool_kernel(const float* __restrict__ att, float* __restrict__ pooled)
{
    int b = blockIdx.x, c = threadIdx.x;
    float s = 0.f;
    for (int t = 0; t < Sn; t++) s += att[(size_t)(b * Sn + t) * HID + c];
    pooled[b * HID + c] = s * (1.f / 256.f);
}

// ---------------------------------------------------------------------------
// cons/hall scalar MLPs: grid 16 = (b,which), 128 threads.
// ---------------------------------------------------------------------------
__global__ void head_mlp_kernel(const float* __restrict__ pooled,
                                const float* __restrict__ cw1, const float* __restrict__ cb1,
                                const float* __restrict__ cw2, const float* __restrict__ cb2,
                                const float* __restrict__ hw1, const float* __restrict__ hb1,
                                const float* __restrict__ hw2, const float* __restrict__ hb2,
                                float* __restrict__ out)
{
    int b = blockIdx.x >> 1;
    int which = blockIdx.x & 1;
    const float* w1 = which ? hw1 : cw1;
    const float* b1 = which ? hb1 : cb1;
    const float* w2 = which ? hw2 : cw2;
    const float* b2 = which ? hb2 : cb2;
    int tid = threadIdx.x;
    __shared__ float p[256];
    p[tid] = pooled[b * HID + tid];
    p[tid + 128] = pooled[b * HID + tid + 128];
    __syncthreads();
    float acc = b1[tid];
    const float* wrow = w1 + (size_t)tid * HID;
#pragma unroll 8
    for (int k = 0; k < HID; k++) acc += p[k] * wrow[k];
    float v = fmaxf(acc, 0.f) * w2[tid];
#pragma unroll
    for (int o = 16; o; o >>= 1) v += __shfl_xor_sync(0xffffffffu, v, o);
    __shared__ float rs[4];
    if ((tid & 31) == 0) rs[tid >> 5] = v;
    __syncthreads();
    if (tid == 0) {
        float sum = rs[0] + rs[1] + rs[2] + rs[3] + b2[0];
        out[which * 8 + b] = 1.f / (1.f + __expf(-sum));
    }
}

// ---------------------------------------------------------------------------
// Zero the diagonal of M.
// ---------------------------------------------------------------------------
__global__ void zero_diag_kernel(float* __restrict__ M)
{
    int b = blockIdx.x, i = threadIdx.x;
    M[(size_t)b * Sn * Sn + (size_t)i * Sn + i] = 0.f;
}

// ---------------------------------------------------------------------------
// Pairwise consistency matrix v2 (float4 smem, no transpose).
//   sc(b,i,j) = sigmoid( sum_c relu(a[b,i,c] + bb[b,j,c] + con_b1[c]) * w2[c] + b2 )
//   M[b,i,j] = M[b,j,i] = sc  for i<j; diag zero.
// grid (tj=8, ti=8, b=8), block 256.
// ---------------------------------------------------------------------------
#define PSTR 260   // padded row stride (floats); 260*4=1040 bytes, 16B aligned
__global__ void pair2_kernel(const float* __restrict__ ga, const float* __restrict__ gb,
                             const float* __restrict__ b1, const float* __restrict__ w2,
                             const float* __restrict__ b2, float* __restrict__ M)
{
    int tj = blockIdx.x, ti = blockIdx.y, b = blockIdx.z;
    if (ti > tj) return;
    extern __shared__ float sm[];
    float* a_s = sm;                   // [32][PSTR]  (bias folded in)
    float* b_s = sm + 32 * PSTR;       // [32][PSTR]
    float* w2s = b_s + 32 * PSTR;      // [256]
    float* scs = w2s + 256;            // [32][33]
    int tid = threadIdx.x;
    {
        int r = tid >> 3;
        int cb = (tid & 7) * 32;
        const float4* asrc = (const float4*)(ga + (size_t)(b * Sn + ti * 32 + r) * HID + cb);
        const float4* bsrc = (const float4*)(gb + (size_t)(b * Sn + tj * 32 + r) * HID + cb);
#pragma unroll
        for (int u = 0; u < 8; u++) {
            int c = cb + u * 4;
            float4 av = asrc[u];
            float4 bb = *(const float4*)(b1 + c);
            av.x += bb.x; av.y += bb.y; av.z += bb.z; av.w += bb.w;
            *(float4*)&a_s[r * PSTR + c] = av;
            *(float4*)&b_s[r * PSTR + c] = bsrc[u];
        }
        w2s[tid] = w2[tid];
    }
    __syncthreads();

    int tx = tid & 31, ty = tid >> 5;  // tx = j-local, ty in 0..7
    float acc[4] = {0.f, 0.f, 0.f, 0.f};
    for (int c = 0; c < 256; c += 4) {
        float4 w = *(const float4*)&w2s[c];
        float4 bv = *(const float4*)&b_s[tx * PSTR + c];
#pragma unroll
        for (int ii = 0; ii < 4; ii++) {
            float4 av = *(const float4*)&a_s[(ty + 8 * ii) * PSTR + c];
            acc[ii] += fmaxf(av.x + bv.x, 0.f) * w.x
                     + fmaxf(av.y + bv.y, 0.f) * w.y
                     + fmaxf(av.z + bv.z, 0.f) * w.z
                     + fmaxf(av.w + bv.w, 0.f) * w.w;
        }
    }
    float bb2 = b2[0];
#pragma unroll
    for (int ii = 0; ii < 4; ii++) {
        int il = ty + 8 * ii;
        float sc = 1.f / (1.f + __expf(-(acc[ii] + bb2)));
        scs[il * 33 + tx] = ((ti * 32 + il) < (tj * 32 + tx)) ? sc : 0.f;
    }
    __syncthreads();

    float* Mb = M + (size_t)b * Sn * Sn;
    bool diag = (ti == tj);
#pragma unroll
    for (int ii = 0; ii < 4; ii++) {
        int il = ty + 8 * ii;
        if (!diag || il < tx)
            Mb[(size_t)(ti * 32 + il) * Sn + tj * 32 + tx] = scs[il * 33 + tx];
        if (!diag || tx < il)
            Mb[(size_t)(tj * 32 + il) * Sn + ti * 32 + tx] = scs[tx * 33 + il];
    }
}

// ---------------------------------------------------------------------------
// Host launcher
// ---------------------------------------------------------------------------
extern "C" void kernel_launch(void* const* d_in, const int* in_sizes, int n_in,
                              void* d_out, int out_size)
{
    (void)in_sizes; (void)n_in; (void)out_size;
    const float* X        = (const float*)d_in[0];
    const float* enc_w1   = (const float*)d_in[1];
    const float* enc_b1   = (const float*)d_in[2];
    const float* ln_g     = (const float*)d_in[3];
    const float* ln_b     = (const float*)d_in[4];
    const float* enc_w2   = (const float*)d_in[5];
    const float* enc_b2   = (const float*)d_in[6];
    const float* in_proj_w= (const float*)d_in[7];
    const float* in_proj_b= (const float*)d_in[8];
    const float* out_w    = (const float*)d_in[9];
    const float* out_b    = (const float*)d_in[10];
    const float* cons_w1  = (const float*)d_in[11];
    const float* cons_b1  = (const float*)d_in[12];
    const float* cons_w2  = (const float*)d_in[13];
    const float* cons_b2  = (const float*)d_in[14];
    const float* hall_w1  = (const float*)d_in[15];
    const float* hall_b1  = (const float*)d_in[16];
    const float* hall_w2  = (const float*)d_in[17];
    const float* hall_b2  = (const float*)d_in[18];
    const float* con_w1   = (const float*)d_in[19];
    const float* con_b1   = (const float*)d_in[20];
    const float* con_w2   = (const float*)d_in[21];
    const float* con_b2   = (const float*)d_in[22];

    float* out = (float*)d_out;
    float* Mout  = out + 16;
    float* AWout = out + 16 + Bn * Sn * Sn;

    float *p_h, *p_r, *p_mf, *p_qkv, *p_ctx, *p_att, *p_a, *p_b, *p_probs, *p_pooled;
    cudaGetSymbolAddress((void**)&p_h, g_h);
    cudaGetSymbolAddress((void**)&p_r, g_r);
    cudaGetSymbolAddress((void**)&p_mf, g_mf);
    cudaGetSymbolAddress((void**)&p_qkv, g_qkv);
    cudaGetSymbolAddress((void**)&p_ctx, g_ctx);
    cudaGetSymbolAddress((void**)&p_att, g_att);
    cudaGetSymbolAddress((void**)&p_a, g_a);
    cudaGetSymbolAddress((void**)&p_b, g_b);
    cudaGetSymbolAddress((void**)&p_probs, g_probs);
    cudaGetSymbolAddress((void**)&p_pooled, g_pooled);

    const int attn_smem = 2 * 256 * 32 * (int)sizeof(float);                 // 64 KB
    const int pair_smem = (2 * 32 * PSTR + 256 + 32 * 33) * (int)sizeof(float); // ~71.8 KB
    cudaFuncSetAttribute(attn2_kernel, cudaFuncAttributeMaxDynamicSharedMemorySize, attn_smem);
    cudaFuncSetAttribute(pair2_kernel, cudaFuncAttributeMaxDynamicSharedMemorySize, pair_smem);

    // 1. h = X @ enc_w1^T + enc_b1          [2048,256] K=512
    gemm2_kernel<<<dim3(HID / 64, ROWS / 64), 128>>>(X, enc_w1, enc_b1, p_h, HID, EMB, EMB);
    // 2. r = relu(LN(h))
    ln_relu_kernel<<<ROWS, 256>>>(p_h, ln_g, ln_b, p_r);
    // 3. mf = r @ enc_w2^T + enc_b2
    gemm2_kernel<<<dim3(HID / 64, ROWS / 64), 128>>>(p_r, enc_w2, enc_b2, p_mf, HID, HID, HID);
    // 4. qkv = mf @ in_proj_w^T + in_proj_b  [2048,768]
    gemm2_kernel<<<dim3(3 * HID / 64, ROWS / 64), 128>>>(p_mf, in_proj_w, in_proj_b, p_qkv, 3 * HID, HID, HID);
    // 5. attention -> ctx, probs (scores stashed then converted in-kernel)
    attn2_kernel<<<128, 128, attn_smem>>>(p_qkv, p_ctx, p_probs);
    // 6. attended = ctx @ out_w^T + out_b
    gemm2_kernel<<<dim3(HID / 64, ROWS / 64), 128>>>(p_ctx, out_w, out_b, p_att, HID, HID, HID);
    // 7. attn_weights (head mean + transpose)
    attnw_kernel<<<dim3(8, 8, 8), dim3(32, 8)>>>(p_probs, AWout);
    // 8. pooled
    pool_kernel<<<Bn, 256>>>(p_att, p_pooled);
    // 9. cons/hall
    head_mlp_kernel<<<16, 128>>>(p_pooled, cons_w1, cons_b1, cons_w2, cons_b2,
                                 hall_w1, hall_b1, hall_w2, hall_b2, out);
    // 10/11. a = mf @ Wa^T, b = mf @ Wb^T  (halves of con_w1 (256x512))
    gemm2_kernel<<<dim3(HID / 64, ROWS / 64), 128>>>(p_mf, con_w1, nullptr, p_a, HID, HID, 2 * HID);
    gemm2_kernel<<<dim3(HID / 64, ROWS / 64), 128>>>(p_mf, con_w1 + HID, nullptr, p_b, HID, HID, 2 * HID);
    // 12. zero diagonal of M
    zero_diag_kernel<<<Bn, Sn>>>(Mout);
    // 13. pairwise M
    pair2_kernel<<<dim3(8, 8, 8), 256, pair_smem>>>(p_a, p_b, con_b1, con_w2, con_b2, Mout);
}

// round 3
// speedup vs baseline: 1.3451x; 1.0834x over previous
#include <cuda_runtime.h>
#include <cuda_bf16.h>
#include <cstddef>

// ---------------------------------------------------------------------------
// Shapes (fixed): B=8, S=256, EMB=512, HID=256, NH=8, DH=32
// Outputs concat: cons[8] | hall[8] | M[8*256*256] | attn_weights[8*256*256]
// ---------------------------------------------------------------------------

#define Bn 8
#define Sn 256
#define EMB 512
#define HID 256
#define NHh 8
#define DHd 32
#define ROWS (Bn*Sn)          // 2048

typedef unsigned long long ULL;

// Packed f32x2 helpers (Blackwell dual-FP32 path; ptxas never auto-emits FFMA2)
__device__ __forceinline__ ULL pk2(float lo, float hi) {
    ULL r; asm("mov.b64 %0,{%1,%2};" : "=l"(r) : "f"(lo), "f"(hi)); return r;
}
__device__ __forceinline__ ULL fma2(ULL a, ULL b, ULL c) {
    ULL d; asm("fma.rn.f32x2 %0,%1,%2,%3;" : "=l"(d) : "l"(a), "l"(b), "l"(c)); return d;
}
__device__ __forceinline__ ULL mul2(ULL a, ULL b) {
    ULL d; asm("mul.rn.f32x2 %0,%1,%2;" : "=l"(d) : "l"(a), "l"(b)); return d;
}
__device__ __forceinline__ void unpk(ULL v, float& lo, float& hi) {
    asm("mov.b64 {%0,%1},%2;" : "=f"(lo), "=f"(hi) : "l"(v));
}

// Scratch (no allocs allowed -> __device__ globals)
__device__ float g_h[ROWS*HID];
__device__ float g_r[ROWS*HID];
__device__ float g_mf[ROWS*HID];
__device__ float g_qkv[ROWS*3*HID];
__device__ float g_ctx[ROWS*HID];
__device__ float g_att[ROWS*HID];
__device__ float g_a[ROWS*HID];
__device__ float g_b[ROWS*HID];
__device__ float g_probs[NHh*Bn*Sn*Sn];   // [h][b][t][s]
__device__ float g_pooled[Bn*HID];

// ---------------------------------------------------------------------------
// GEMM core: C_tile[64,64] = A_tile[64,K] @ W_tile^T (+bias), fp32 via f32x2.
//   128 threads, 8x4 microtile (4 packed row-pairs x 4 cols), BK=16,
//   double-buffered smem, register prefetch.
//   Ablk = A + row0*K ; Wblk = W + col0*ldw ; Cblk = C + row0*ldc + col0.
// ---------------------------------------------------------------------------
__device__ __forceinline__ void gemm_core(const float* __restrict__ Ablk,
                                          const float* __restrict__ Wblk,
                                          int ldw,
                                          const float* __restrict__ biasblk,
                                          float* __restrict__ Cblk,
                                          int ldc, int K)
{
    __shared__ __align__(16) float As[2][16][68];
    __shared__ __align__(16) float Ws[2][16][68];
    const int tid = threadIdx.x;
    const int lrow = tid & 63;
    const int lk = (tid >> 6) << 3;   // 0 or 8
    const float* Ap = Ablk + (size_t)lrow * K + lk;
    const float* Wp = Wblk + (size_t)lrow * ldw + lk;
    const int tx = tid & 15;          // 4 cols each
    const int ty = tid >> 4;          // 8 rows each (4 packed pairs)

    ULL acc[4][4];
#pragma unroll
    for (int u = 0; u < 4; u++)
#pragma unroll
        for (int j = 0; j < 4; j++) acc[u][j] = 0ULL;

    float4 a0 = *(const float4*)(Ap);
    float4 a1 = *(const float4*)(Ap + 4);
    float4 w0 = *(const float4*)(Wp);
    float4 w1 = *(const float4*)(Wp + 4);
    As[0][lk + 0][lrow] = a0.x; As[0][lk + 1][lrow] = a0.y;
    As[0][lk + 2][lrow] = a0.z; As[0][lk + 3][lrow] = a0.w;
    As[0][lk + 4][lrow] = a1.x; As[0][lk + 5][lrow] = a1.y;
    As[0][lk + 6][lrow] = a1.z; As[0][lk + 7][lrow] = a1.w;
    Ws[0][lk + 0][lrow] = w0.x; Ws[0][lk + 1][lrow] = w0.y;
    Ws[0][lk + 2][lrow] = w0.z; Ws[0][lk + 3][lrow] = w0.w;
    Ws[0][lk + 4][lrow] = w1.x; Ws[0][lk + 5][lrow] = w1.y;
    Ws[0][lk + 6][lrow] = w1.z; Ws[0][lk + 7][lrow] = w1.w;
    __syncthreads();

    const int nt = K >> 4;
    for (int t = 0; t < nt; ++t) {
        const int cur = t & 1;
        if (t + 1 < nt) {
            const float* Ap2 = Ap + ((t + 1) << 4);
            const float* Wp2 = Wp + ((t + 1) << 4);
            a0 = *(const float4*)(Ap2);
            a1 = *(const float4*)(Ap2 + 4);
            w0 = *(const float4*)(Wp2);
            w1 = *(const float4*)(Wp2 + 4);
        }
#pragma unroll
        for (int kk = 0; kk < 16; ++kk) {
            // A row-pairs, packed straight out of smem
            ulonglong2 aA = *(const ulonglong2*)&As[cur][kk][ty << 3];
            ulonglong2 aB = *(const ulonglong2*)&As[cur][kk][(ty << 3) + 4];
            float4 bf = *(const float4*)&Ws[cur][kk][tx << 2];
            ULL b0 = pk2(bf.x, bf.x);
            ULL b1 = pk2(bf.y, bf.y);
            ULL b2 = pk2(bf.z, bf.z);
            ULL b3 = pk2(bf.w, bf.w);
            ULL ar[4] = {aA.x, aA.y, aB.x, aB.y};
#pragma unroll
            for (int u = 0; u < 4; u++) {
                acc[u][0] = fma2(ar[u], b0, acc[u][0]);
                acc[u][1] = fma2(ar[u], b1, acc[u][1]);
                acc[u][2] = fma2(ar[u], b2, acc[u][2]);
                acc[u][3] = fma2(ar[u], b3, acc[u][3]);
            }
        }
        if (t + 1 < nt) {
            const int nb = (t + 1) & 1;
            As[nb][lk + 0][lrow] = a0.x; As[nb][lk + 1][lrow] = a0.y;
            As[nb][lk + 2][lrow] = a0.z; As[nb][lk + 3][lrow] = a0.w;
            As[nb][lk + 4][lrow] = a1.x; As[nb][lk + 5][lrow] = a1.y;
            As[nb][lk + 6][lrow] = a1.z; As[nb][lk + 7][lrow] = a1.w;
            Ws[nb][lk + 0][lrow] = w0.x; Ws[nb][lk + 1][lrow] = w0.y;
            Ws[nb][lk + 2][lrow] = w0.z; Ws[nb][lk + 3][lrow] = w0.w;
            Ws[nb][lk + 4][lrow] = w1.x; Ws[nb][lk + 5][lrow] = w1.y;
            Ws[nb][lk + 6][lrow] = w1.z; Ws[nb][lk + 7][lrow] = w1.w;
            __syncthreads();
        }
    }

    float4 bz = make_float4(0.f, 0.f, 0.f, 0.f);
    if (biasblk) bz = *(const float4*)(biasblk + (tx << 2));
#pragma unroll
    for (int u = 0; u < 4; u++) {
        float4 lo4, hi4;
        unpk(acc[u][0], lo4.x, hi4.x);
        unpk(acc[u][1], lo4.y, hi4.y);
        unpk(acc[u][2], lo4.z, hi4.z);
        unpk(acc[u][3], lo4.w, hi4.w);
        lo4.x += bz.x; lo4.y += bz.y; lo4.z += bz.z; lo4.w += bz.w;
        hi4.x += bz.x; hi4.y += bz.y; hi4.z += bz.z; hi4.w += bz.w;
        int r0 = (ty << 3) + 2 * u;
        *(float4*)(Cblk + (size_t)r0 * ldc + (tx << 2)) = lo4;
        *(float4*)(Cblk + (size_t)(r0 + 1) * ldc + (tx << 2)) = hi4;
    }
}

// Standalone GEMM: C[M,N] = A[M,K] @ W^T + bias, W is [N][ldw]
__global__ __launch_bounds__(128) void gemm3_kernel(const float* __restrict__ A,
                                                    const float* __restrict__ W,
                                                    const float* __restrict__ bias,
                                                    float* __restrict__ C,
                                                    int N, int K, int ldw)
{
    int row0 = blockIdx.y << 6;
    int col0 = blockIdx.x << 6;
    gemm_core(A + (size_t)row0 * K,
              W + (size_t)col0 * ldw, ldw,
              bias ? bias + col0 : nullptr,
              C + (size_t)row0 * N + col0, N, K);
}

// Fused GEMM: from mf compute qkv (cols 0..767), a (768..1023), b (1024..1279)
__global__ __launch_bounds__(128) void gemm_fused_kernel(const float* __restrict__ mf,
                                                         const float* __restrict__ in_proj_w,
                                                         const float* __restrict__ in_proj_b,
                                                         const float* __restrict__ con_w1,
                                                         float* __restrict__ qkv,
                                                         float* __restrict__ a,
                                                         float* __restrict__ b)
{
    int row0 = blockIdx.y << 6;
    int cb = blockIdx.x;              // 0..19
    const float* Wblk; const float* biasblk; float* Cblk; int ldw, ldc;
    if (cb < 12) {
        int n0 = cb * 64;
        Wblk = in_proj_w + (size_t)n0 * HID; ldw = HID;
        biasblk = in_proj_b + n0;
        Cblk = qkv + (size_t)row0 * (3 * HID) + n0; ldc = 3 * HID;
    } else if (cb < 16) {
        int n0 = (cb - 12) * 64;
        Wblk = con_w1 + (size_t)n0 * (2 * HID); ldw = 2 * HID;
        biasblk = nullptr;
        Cblk = a + (size_t)row0 * HID + n0; ldc = HID;
    } else {
        int n0 = (cb - 16) * 64;
        Wblk = con_w1 + (size_t)n0 * (2 * HID) + HID; ldw = 2 * HID;
        biasblk = nullptr;
        Cblk = b + (size_t)row0 * HID + n0; ldc = HID;
    }
    gemm_core(mf + (size_t)row0 * HID, Wblk, ldw, biasblk, Cblk, ldc, HID);
}

// ---------------------------------------------------------------------------
// LayerNorm(HID=256) + ReLU, one block per row.
// ---------------------------------------------------------------------------
__global__ void ln_relu_kernel(const float* __restrict__ h,
                               const float* __restrict__ g,
                               const float* __restrict__ beta,
                               float* __restrict__ out)
{
    int row = blockIdx.x;
    int c = threadIdx.x;
    float v = h[(size_t)row * HID + c];
    float s = v, s2 = v * v;
#pragma unroll
    for (int o = 16; o; o >>= 1) {
        s  += __shfl_xor_sync(0xffffffffu, s, o);
        s2 += __shfl_xor_sync(0xffffffffu, s2, o);
    }
    __shared__ float rs[8], rs2[8];
    if ((c & 31) == 0) { rs[c >> 5] = s; rs2[c >> 5] = s2; }
    __syncthreads();
    float tot = 0.f, tot2 = 0.f;
#pragma unroll
    for (int w = 0; w < 8; w++) { tot += rs[w]; tot2 += rs2[w]; }
    float mu = tot * (1.f / 256.f);
    float var = tot2 * (1.f / 256.f) - mu * mu;
    float y = (v - mu) * rsqrtf(var + 1e-5f) * g[c] + beta[c];
    out[(size_t)row * HID + c] = fmaxf(y, 0.f);
}

// ---------------------------------------------------------------------------
// Attention (f32x2): grid = 128 blocks (2 query-halves x 64 (b,h)), 128 thr.
// Pass 1: online softmax -> ctx, raw scaled scores stashed in probs buffer.
// Pass 2: reload score, write exp(score - m)/l/NH.
// ---------------------------------------------------------------------------
__global__ __launch_bounds__(128) void attn2_kernel(const float* __restrict__ qkv,
                                                    float* __restrict__ ctx,
                                                    float* __restrict__ probs)
{
    extern __shared__ float sm[];
    float* Ks = sm;             // [256][32]
    float* Vs = sm + 256 * 32;  // [256][32]
    int bh = blockIdx.x >> 1;
    int half = blockIdx.x & 1;
    int b = bh >> 3, hd = bh & 7;
    int tid = threadIdx.x;         // 128
    int s = (half << 7) + tid;
    const float* base = qkv + (size_t)(b * Sn) * (3 * HID) + hd * DHd;

#pragma unroll
    for (int rr = 0; rr < 2; rr++) {
        int r = tid + rr * 128;
        const float4* krow = (const float4*)(base + (size_t)r * (3 * HID) + HID);
        const float4* vrow = (const float4*)(base + (size_t)r * (3 * HID) + 2 * HID);
        float4* kd = (float4*)(Ks + r * 32);
        float4* vd = (float4*)(Vs + r * 32);
#pragma unroll
        for (int i = 0; i < 8; i++) { kd[i] = krow[i]; vd[i] = vrow[i]; }
    }
    ULL q2[16];
    {
        const ulonglong2* qrow = (const ulonglong2*)(base + (size_t)s * (3 * HID));
#pragma unroll
        for (int u = 0; u < 8; u++) {
            ulonglong2 qv = qrow[u];
            q2[2 * u] = qv.x; q2[2 * u + 1] = qv.y;
        }
    }
    __syncthreads();

    const float scale = 0.17677669529663687f;   // 1/sqrt(32)
    float m = -1e30f, l = 0.f;
    ULL acc2[16];
#pragma unroll
    for (int d = 0; d < 16; d++) acc2[d] = 0ULL;

    float* pb = probs + ((size_t)(hd * Bn + b) * Sn) * Sn + s;

    for (int t = 0; t < Sn; t++) {
        const ulonglong2* k4 = (const ulonglong2*)(Ks + t * 32);
        ULL sd2 = 0ULL;
#pragma unroll
        for (int u = 0; u < 8; u++) {
            ulonglong2 kv = k4[u];
            sd2 = fma2(q2[2 * u], kv.x, sd2);
            sd2 = fma2(q2[2 * u + 1], kv.y, sd2);
        }
        float slo, shi;
        unpk(sd2, slo, shi);
        float sd = (slo + shi) * scale;
        pb[(size_t)t * Sn] = sd;          // stash raw score
        float mn = fmaxf(m, sd);
        float corr = __expf(m - mn);
        float p = __expf(sd - mn);
        l = l * corr + p;
        ULL corr2 = pk2(corr, corr);
        ULL p2 = pk2(p, p);
        const ulonglong2* v4 = (const ulonglong2*)(Vs + t * 32);
#pragma unroll
        for (int u = 0; u < 8; u++) {
            ulonglong2 vv = v4[u];
            acc2[2 * u]     = fma2(p2, vv.x, mul2(acc2[2 * u], corr2));
            acc2[2 * u + 1] = fma2(p2, vv.y, mul2(acc2[2 * u + 1], corr2));
        }
        m = mn;
    }
    float invl = 1.f / l;
    ULL invl2 = pk2(invl, invl);
    ulonglong2* crow = (ulonglong2*)(ctx + (size_t)(b * Sn + s) * HID + hd * DHd);
#pragma unroll
    for (int u = 0; u < 8; u++) {
        ulonglong2 ov;
        ov.x = mul2(acc2[2 * u], invl2);
        ov.y = mul2(acc2[2 * u + 1], invl2);
        crow[u] = ov;
    }

    // pass 2: convert stashed scores to probs/NH
    float c1 = invl * 0.125f;
    for (int t = 0; t < Sn; t++) {
        float sc = pb[(size_t)t * Sn];
        pb[(size_t)t * Sn] = __expf(sc - m) * c1;
    }
}

// ---------------------------------------------------------------------------
// attn_weights[b][s][t] = sum_h probs[h][b][t][s]   (transpose via smem tile)
// ---------------------------------------------------------------------------
__global__ void attnw_kernel(const float* __restrict__ probs,
                             float* __restrict__ out)
{
    __shared__ float tile[32][33];
    int b = blockIdx.z, t0 = blockIdx.x * 32, s0 = blockIdx.y * 32;
    int tx = threadIdx.x, ty = threadIdx.y;
#pragma unroll
    for (int r = 0; r < 4; r++) {
        int t = t0 + ty + r * 8;
        float sum = 0.f;
#pragma unroll
        for (int h = 0; h < 8; h++)
            sum += probs[((size_t)(h * Bn + b) * Sn + t) * Sn + s0 + tx];
        tile[ty + r * 8][tx] = sum;
    }
    __syncthreads();
#pragma unroll
    for (int r = 0; r < 4; r++) {
        int srow = s0 + ty + r * 8;
        out[((size_t)b * Sn + srow) * Sn + t0 + tx] = tile[tx][ty + r * 8];
    }
}

// ---------------------------------------------------------------------------
// pooled[b][c] = mean_s attended[b][s][c]
// ---------------------------------------------------------------------------
__global__ void pool_kernel(const float* __restrict__ att, float* __restrict__ pooled)
{
    int b = blockIdx.x, c = threadIdx.x;
    float s = 0.f;
    for (int t = 0; t < Sn; t++) s += att[(size_t)(b * Sn + t) * HID + c];
    pooled[b * HID + c] = s * (1.f / 256.f);
}

// ---------------------------------------------------------------------------
// cons/hall scalar MLPs: grid 16 = (b,which), 128 threads.
// ---------------------------------------------------------------------------
__global__ void head_mlp_kernel(const float* __restrict__ pooled,
                                const float* __restrict__ cw1, const float* __restrict__ cb1,
                                const float* __restrict__ cw2, const float* __restrict__ cb2,
                                const float* __restrict__ hw1, const float* __restrict__ hb1,
                                const float* __restrict__ hw2, const float* __restrict__ hb2,
                                float* __restrict__ out)
{
    int b = blockIdx.x >> 1;
    int which = blockIdx.x & 1;
    const float* w1 = which ? hw1 : cw1;
    const float* b1 = which ? hb1 : cb1;
    const float* w2 = which ? hw2 : cw2;
    const float* b2 = which ? hb2 : cb2;
    int tid = threadIdx.x;
    __shared__ float p[256];
    p[tid] = pooled[b * HID + tid];
    p[tid + 128] = pooled[b * HID + tid + 128];
    __syncthreads();
    float acc = b1[tid];
    const float* wrow = w1 + (size_t)tid * HID;
#pragma unroll 8
    for (int k = 0; k < HID; k++) acc += p[k] * wrow[k];
    float v = fmaxf(acc, 0.f) * w2[tid];
#pragma unroll
    for (int o = 16; o; o >>= 1) v += __shfl_xor_sync(0xffffffffu, v, o);
    __shared__ float rs[4];
    if ((tid & 31) == 0) rs[tid >> 5] = v;
    __syncthreads();
    if (tid == 0) {
        float sum = rs[0] + rs[1] + rs[2] + rs[3] + b2[0];
        out[which * 8 + b] = 1.f / (1.f + __expf(-sum));
    }
}

// ---------------------------------------------------------------------------
// Zero the diagonal of M.
// ---------------------------------------------------------------------------
__global__ void zero_diag_kernel(float* __restrict__ M)
{
    int b = blockIdx.x, i = threadIdx.x;
    M[(size_t)b * Sn * Sn + (size_t)i * Sn + i] = 0.f;
}

// ---------------------------------------------------------------------------
// Pairwise consistency matrix (float4 smem).
// ---------------------------------------------------------------------------
#define PSTR 260
__global__ void pair2_kernel(const float* __restrict__ ga, const float* __restrict__ gb,
                             const float* __restrict__ b1, const float* __restrict__ w2,
                             const float* __restrict__ b2, float* __restrict__ M)
{
    int tj = blockIdx.x, ti = blockIdx.y, b = blockIdx.z;
    if (ti > tj) return;
    extern __shared__ float sm[];
    float* a_s = sm;                   // [32][PSTR]  (bias folded in)
    float* b_s = sm + 32 * PSTR;       // [32][PSTR]
    float* w2s = b_s + 32 * PSTR;      // [256]
    float* scs = w2s + 256;            // [32][33]
    int tid = threadIdx.x;
    {
        int r = tid >> 3;
        int cb = (tid & 7) * 32;
        const float4* asrc = (const float4*)(ga + (size_t)(b * Sn + ti * 32 + r) * HID + cb);
        const float4* bsrc = (const float4*)(gb + (size_t)(b * Sn + tj * 32 + r) * HID + cb);
#pragma unroll
        for (int u = 0; u < 8; u++) {
            int c = cb + u * 4;
            float4 av = asrc[u];
            float4 bb = *(const float4*)(b1 + c);
            av.x += bb.x; av.y += bb.y; av.z += bb.z; av.w += bb.w;
            *(float4*)&a_s[r * PSTR + c] = av;
            *(float4*)&b_s[r * PSTR + c] = bsrc[u];
        }
        w2s[tid] = w2[tid];
    }
    __syncthreads();

    int tx = tid & 31, ty = tid >> 5;
    float acc[4] = {0.f, 0.f, 0.f, 0.f};
    for (int c = 0; c < 256; c += 4) {
        float4 w = *(const float4*)&w2s[c];
        float4 bv = *(const float4*)&b_s[tx * PSTR + c];
#pragma unroll
        for (int ii = 0; ii < 4; ii++) {
            float4 av = *(const float4*)&a_s[(ty + 8 * ii) * PSTR + c];
            acc[ii] += fmaxf(av.x + bv.x, 0.f) * w.x
                     + fmaxf(av.y + bv.y, 0.f) * w.y
                     + fmaxf(av.z + bv.z, 0.f) * w.z
                     + fmaxf(av.w + bv.w, 0.f) * w.w;
        }
    }
    float bb2 = b2[0];
#pragma unroll
    for (int ii = 0; ii < 4; ii++) {
        int il = ty + 8 * ii;
        float sc = 1.f / (1.f + __expf(-(acc[ii] + bb2)));
        scs[il * 33 + tx] = ((ti * 32 + il) < (tj * 32 + tx)) ? sc : 0.f;
    }
    __syncthreads();

    float* Mb = M + (size_t)b * Sn * Sn;
    bool diag = (ti == tj);
#pragma unroll
    for (int ii = 0; ii < 4; ii++) {
        int il = ty + 8 * ii;
        if (!diag || il < tx)
            Mb[(size_t)(ti * 32 + il) * Sn + tj * 32 + tx] = scs[il * 33 + tx];
        if (!diag || tx < il)
            Mb[(size_t)(tj * 32 + il) * Sn + ti * 32 + tx] = scs[tx * 33 + il];
    }
}

// ---------------------------------------------------------------------------
// Host launcher
// ---------------------------------------------------------------------------
extern "C" void kernel_launch(void* const* d_in, const int* in_sizes, int n_in,
                              void* d_out, int out_size)
{
    (void)in_sizes; (void)n_in; (void)out_size;
    const float* X        = (const float*)d_in[0];
    const float* enc_w1   = (const float*)d_in[1];
    const float* enc_b1   = (const float*)d_in[2];
    const float* ln_g     = (const float*)d_in[3];
    const float* ln_b     = (const float*)d_in[4];
    const float* enc_w2   = (const float*)d_in[5];
    const float* enc_b2   = (const float*)d_in[6];
    const float* in_proj_w= (const float*)d_in[7];
    const float* in_proj_b= (const float*)d_in[8];
    const float* out_w    = (const float*)d_in[9];
    const float* out_b    = (const float*)d_in[10];
    const float* cons_w1  = (const float*)d_in[11];
    const float* cons_b1  = (const float*)d_in[12];
    const float* cons_w2  = (const float*)d_in[13];
    const float* cons_b2  = (const float*)d_in[14];
    const float* hall_w1  = (const float*)d_in[15];
    const float* hall_b1  = (const float*)d_in[16];
    const float* hall_w2  = (const float*)d_in[17];
    const float* hall_b2  = (const float*)d_in[18];
    const float* con_w1   = (const float*)d_in[19];
    const float* con_b1   = (const float*)d_in[20];
    const float* con_w2   = (const float*)d_in[21];
    const float* con_b2   = (const float*)d_in[22];

    float* out = (float*)d_out;
    float* Mout  = out + 16;
    float* AWout = out + 16 + Bn * Sn * Sn;

    float *p_h, *p_r, *p_mf, *p_qkv, *p_ctx, *p_att, *p_a, *p_b, *p_probs, *p_pooled;
    cudaGetSymbolAddress((void**)&p_h, g_h);
    cudaGetSymbolAddress((void**)&p_r, g_r);
    cudaGetSymbolAddress((void**)&p_mf, g_mf);
    cudaGetSymbolAddress((void**)&p_qkv, g_qkv);
    cudaGetSymbolAddress((void**)&p_ctx, g_ctx);
    cudaGetSymbolAddress((void**)&p_att, g_att);
    cudaGetSymbolAddress((void**)&p_a, g_a);
    cudaGetSymbolAddress((void**)&p_b, g_b);
    cudaGetSymbolAddress((void**)&p_probs, g_probs);
    cudaGetSymbolAddress((void**)&p_pooled, g_pooled);

    const int attn_smem = 2 * 256 * 32 * (int)sizeof(float);                    // 64 KB
    const int pair_smem = (2 * 32 * PSTR + 256 + 32 * 33) * (int)sizeof(float); // ~71.8 KB
    cudaFuncSetAttribute(attn2_kernel, cudaFuncAttributeMaxDynamicSharedMemorySize, attn_smem);
    cudaFuncSetAttribute(pair2_kernel, cudaFuncAttributeMaxDynamicSharedMemorySize, pair_smem);

    // 1. h = X @ enc_w1^T + enc_b1          [2048,256] K=512
    gemm3_kernel<<<dim3(HID / 64, ROWS / 64), 128>>>(X, enc_w1, enc_b1, p_h, HID, EMB, EMB);
    // 2. r = relu(LN(h))
    ln_relu_kernel<<<ROWS, 256>>>(p_h, ln_g, ln_b, p_r);
    // 3. mf = r @ enc_w2^T + enc_b2
    gemm3_kernel<<<dim3(HID / 64, ROWS / 64), 128>>>(p_r, enc_w2, enc_b2, p_mf, HID, HID, HID);
    // 4. fused: qkv | a | b  from mf         [2048,1280]
    gemm_fused_kernel<<<dim3(20, ROWS / 64), 128>>>(p_mf, in_proj_w, in_proj_b, con_w1,
                                                    p_qkv, p_a, p_b);
    // 5. attention -> ctx, probs
    attn2_kernel<<<128, 128, attn_smem>>>(p_qkv, p_ctx, p_probs);
    // 6. attended = ctx @ out_w^T + out_b
    gemm3_kernel<<<dim3(HID / 64, ROWS / 64), 128>>>(p_ctx, out_w, out_b, p_att, HID, HID, HID);
    // 7. attn_weights (head mean + transpose)
    attnw_kernel<<<dim3(8, 8, 8), dim3(32, 8)>>>(p_probs, AWout);
    // 8. pooled
    pool_kernel<<<Bn, 256>>>(p_att, p_pooled);
    // 9. cons/hall
    head_mlp_kernel<<<16, 128>>>(p_pooled, cons_w1, cons_b1, cons_w2, cons_b2,
                                 hall_w1, hall_b1, hall_w2, hall_b2, out);
    // 10. zero diagonal of M
    zero_diag_kernel<<<Bn, Sn>>>(Mout);
    // 11. pairwise M
    pair2_kernel<<<dim3(8, 8, 8), 256, pair_smem>>>(p_a, p_b, con_b1, con_w2, con_b2, Mout);
}